// round 3
// baseline (speedup 1.0000x reference)
#include <cuda_runtime.h>

// Problem constants (fixed by setup_inputs)
#define F_DIM    16384
#define BINS     128
#define FEAT     (2*BINS + 1)     // 257
#define OUT_DIM  64
#define MAXB     4096

// ---- kernel 1: per-row histogram features ----
#define NTHREADS 512
#define NWARPS   (NTHREADS/32)    // 16
#define VPT      (F_DIM/NTHREADS) // 32 values per thread

// feats scratch: [B, 257] fp32 (static device global; no allocation)
__device__ float g_feats[(size_t)MAXB * FEAT];

extern __shared__ unsigned char smem_raw[];

__global__ __launch_bounds__(NTHREADS)
void hist_feats_kernel(const float* __restrict__ x)
{
    float* s_data = (float*)smem_raw;                                   // 16384 f
    int*   s_hist = (int*)(smem_raw + (size_t)F_DIM * 4);               // 16*128 i
    float* s_wmin = (float*)(smem_raw + (size_t)F_DIM * 4 + (size_t)NWARPS * BINS * 4);
    float* s_wmax = s_wmin + NWARPS;

    const int t    = threadIdx.x;
    const int wid  = t >> 5;
    const int lane = t & 31;
    const int row  = blockIdx.x;

    // zero per-warp histograms (independent of the load below)
    #pragma unroll
    for (int i = t; i < NWARPS * BINS; i += NTHREADS) s_hist[i] = 0;

    // Pass A: stream row HBM -> SMEM (float4), track min/max in flight
    const float4* xr = (const float4*)(x + (size_t)row * F_DIM);
    float4* s4 = (float4*)s_data;
    float lmin =  3.402823e38f;
    float lmax = -3.402823e38f;
    #pragma unroll
    for (int k = 0; k < VPT / 4; k++) {
        float4 v = xr[t + k * NTHREADS];
        s4[t + k * NTHREADS] = v;
        lmin = fminf(lmin, fminf(fminf(v.x, v.y), fminf(v.z, v.w)));
        lmax = fmaxf(lmax, fmaxf(fmaxf(v.x, v.y), fmaxf(v.z, v.w)));
    }
    // warp reduce min/max
    #pragma unroll
    for (int s = 16; s; s >>= 1) {
        lmin = fminf(lmin, __shfl_xor_sync(0xffffffffu, lmin, s));
        lmax = fmaxf(lmax, __shfl_xor_sync(0xffffffffu, lmax, s));
    }
    if (lane == 0) { s_wmin[wid] = lmin; s_wmax[wid] = lmax; }
    __syncthreads();

    // block min/max (every thread reads the 16 partials - cheap, no extra sync)
    float mn = s_wmin[0], mx = s_wmax[0];
    #pragma unroll
    for (int i = 1; i < NWARPS; i++) {
        mn = fminf(mn, s_wmin[i]);
        mx = fmaxf(mx, s_wmax[i]);
    }
    const float width = mx - mn;
    const float scale = (width > 0.0f) ? ((float)BINS / width) : 0.0f;

    // Pass B: histogram from SMEM, per-warp privatized counters
    int* hw = s_hist + wid * BINS;
    #pragma unroll
    for (int k = 0; k < VPT / 4; k++) {
        float4 v = s4[t + k * NTHREADS];
        // (v - mn) >= 0 always, so int-truncation == floor; clamp top bin
        int b0 = min(BINS - 1, (int)((v.x - mn) * scale));
        int b1 = min(BINS - 1, (int)((v.y - mn) * scale));
        int b2 = min(BINS - 1, (int)((v.z - mn) * scale));
        int b3 = min(BINS - 1, (int)((v.w - mn) * scale));
        atomicAdd(&hw[b0], 1);
        atomicAdd(&hw[b1], 1);
        atomicAdd(&hw[b2], 1);
        atomicAdd(&hw[b3], 1);
    }
    __syncthreads();

    // reduce per-warp histograms + emit feats row
    float* outf = g_feats + (size_t)row * FEAT;
    if (t < BINS) {
        int c = 0;
        #pragma unroll
        for (int w = 0; w < NWARPS; w++) c += s_hist[w * BINS + t];
        outf[t] = (float)c * (1.0f / (float)F_DIM);   // density: sum == F exactly
    } else if (t < BINS + BINS + 1) {
        int i = t - BINS;
        outf[BINS + i] = mn + ((float)i * (1.0f / (float)BINS)) * width;
    }
}

// ---- kernel 2: out[B,64] = feats[B,257] @ W^T + b, W staged in SMEM ----
#define K2_ROWS 16
#define K2_T    (K2_ROWS * OUT_DIM)   // 1024 threads

__global__ __launch_bounds__(K2_T)
void feats_gemm_kernel(const float* __restrict__ W,
                       const float* __restrict__ bias,
                       float* __restrict__ out, int B)
{
    float* sW = (float*)smem_raw;                    // 64*257 f = 65792 B
    float* sF = sW + (size_t)OUT_DIM * FEAT;         // 16*257 f = 16448 B

    const int t = threadIdx.x;
    const int row0 = blockIdx.x * K2_ROWS;

    // cooperative loads
    for (int i = t; i < OUT_DIM * FEAT; i += K2_T) sW[i] = W[i];
    const float* fin = g_feats + (size_t)row0 * FEAT;
    int nrows = min(K2_ROWS, B - row0);
    for (int i = t; i < nrows * FEAT; i += K2_T) sF[i] = fin[i];
    __syncthreads();

    const int r = t >> 6;       // local row 0..15 (same r across a warp)
    const int o = t & 63;       // output col (distinct per lane -> stride 257: conflict-free)
    const int row = row0 + r;
    if (row >= B) return;

    const float* fr = sF + r * FEAT;
    const float* wr = sW + o * FEAT;
    float acc = bias[o];
    #pragma unroll 4
    for (int j = 0; j < FEAT; j++) {
        acc = fmaf(fr[j], wr[j], acc);
    }
    out[(size_t)row * OUT_DIM + o] = acc;
}

extern "C" void kernel_launch(void* const* d_in, const int* in_sizes, int n_in,
                              void* d_out, int out_size)
{
    const float* x = (const float*)d_in[0];
    const float* W = (const float*)d_in[1];
    const float* b = (const float*)d_in[2];
    float* out = (float*)d_out;

    const int B = in_sizes[0] / F_DIM;

    const size_t sm1 = (size_t)F_DIM * 4 + (size_t)NWARPS * BINS * 4 + 2 * NWARPS * 4; // 73856
    const size_t sm2 = (size_t)OUT_DIM * FEAT * 4 + (size_t)K2_ROWS * FEAT * 4;        // 82240

    cudaFuncSetAttribute(hist_feats_kernel,
                         cudaFuncAttributeMaxDynamicSharedMemorySize, (int)sm1);
    cudaFuncSetAttribute(feats_gemm_kernel,
                         cudaFuncAttributeMaxDynamicSharedMemorySize, (int)sm2);

    hist_feats_kernel<<<B, NTHREADS, sm1>>>(x);
    feats_gemm_kernel<<<(B + K2_ROWS - 1) / K2_ROWS, K2_T, sm2>>>(W, b, out, B);
}

// round 7
// speedup vs baseline: 1.3014x; 1.3014x over previous
#include <cuda_runtime.h>

// Problem constants (fixed by setup_inputs)
#define F_DIM    16384
#define BINS     128
#define FEAT     (2*BINS + 1)     // 257
#define OUT_DIM  64
#define MAXB     4096

// ---- kernel 1: per-row histogram features ----
#define NTHREADS 512
#define NWARPS   (NTHREADS/32)    // 16
#define VPT      (F_DIM/NTHREADS) // 32 values per thread (8 float4)

// feats scratch: [B, 257] fp32 (static device global; no allocation)
__device__ float g_feats[(size_t)MAXB * FEAT];

extern __shared__ unsigned char smem_raw[];

__global__ __launch_bounds__(NTHREADS)
void hist_feats_kernel(const float* __restrict__ x)
{
    // smem: per-warp histograms + warp min/max partials (NO data staging:
    // each thread re-bins its own register-resident values)
    int*   s_hist = (int*)smem_raw;                       // 16*128 ints = 8192 B
    float* s_wmin = (float*)(smem_raw + (size_t)NWARPS * BINS * 4);
    float* s_wmax = s_wmin + NWARPS;

    const int t    = threadIdx.x;
    const int wid  = t >> 5;
    const int lane = t & 31;
    const int row  = blockIdx.x;

    // zero per-warp histograms
    #pragma unroll
    for (int i = t; i < NWARPS * BINS; i += NTHREADS) s_hist[i] = 0;

    // Pass A: stream row HBM -> registers (float4), track min/max in flight
    const float4* xr = (const float4*)(x + (size_t)row * F_DIM);
    float4 v[VPT / 4];
    float lmin =  3.402823e38f;
    float lmax = -3.402823e38f;
    #pragma unroll
    for (int k = 0; k < VPT / 4; k++) {
        v[k] = xr[t + k * NTHREADS];
        lmin = fminf(lmin, fminf(fminf(v[k].x, v[k].y), fminf(v[k].z, v[k].w)));
        lmax = fmaxf(lmax, fmaxf(fmaxf(v[k].x, v[k].y), fmaxf(v[k].z, v[k].w)));
    }
    // warp reduce min/max
    #pragma unroll
    for (int s = 16; s; s >>= 1) {
        lmin = fminf(lmin, __shfl_xor_sync(0xffffffffu, lmin, s));
        lmax = fmaxf(lmax, __shfl_xor_sync(0xffffffffu, lmax, s));
    }
    if (lane == 0) { s_wmin[wid] = lmin; s_wmax[wid] = lmax; }
    __syncthreads();

    // block min/max
    float mn = s_wmin[0], mx = s_wmax[0];
    #pragma unroll
    for (int i = 1; i < NWARPS; i++) {
        mn = fminf(mn, s_wmin[i]);
        mx = fmaxf(mx, s_wmax[i]);
    }
    const float width = mx - mn;
    const float scale = (width > 0.0f) ? ((float)BINS / width) : 0.0f;

    // Pass B: histogram straight from registers, per-warp privatized counters
    int* hw = s_hist + wid * BINS;
    #pragma unroll
    for (int k = 0; k < VPT / 4; k++) {
        // (v - mn) >= 0 always, so int-truncation == floor; clamp top bin
        int b0 = min(BINS - 1, (int)((v[k].x - mn) * scale));
        int b1 = min(BINS - 1, (int)((v[k].y - mn) * scale));
        int b2 = min(BINS - 1, (int)((v[k].z - mn) * scale));
        int b3 = min(BINS - 1, (int)((v[k].w - mn) * scale));
        atomicAdd(&hw[b0], 1);
        atomicAdd(&hw[b1], 1);
        atomicAdd(&hw[b2], 1);
        atomicAdd(&hw[b3], 1);
    }
    __syncthreads();

    // reduce per-warp histograms + emit feats row
    float* outf = g_feats + (size_t)row * FEAT;
    if (t < BINS) {
        int c = 0;
        #pragma unroll
        for (int w = 0; w < NWARPS; w++) c += s_hist[w * BINS + t];
        outf[t] = (float)c * (1.0f / (float)F_DIM);   // density: sum == F exactly
    } else if (t < BINS + BINS + 1) {
        int i = t - BINS;
        outf[BINS + i] = mn + ((float)i * (1.0f / (float)BINS)) * width;
    }
}

// ---- kernel 2: out[B,64] = feats[B,257] @ W^T + b ----
// Register-blocked: tile M=32 x N=64 per block, 256 threads, 4x2 outputs each.
// Smem tiles stored k-major with padded strides for conflict-free reads:
//   sWt[k][66] (cols 0..63 used), sFt[k][36] (rows 0..31 used)
#define K2_TM   32
#define K2_T    256
#define WT_STRIDE 66
#define FT_STRIDE 36
// sFt offset in floats, rounded up to a 16-byte (4-float) boundary so that
// float4 loads from sFt are aligned (FEAT*WT_STRIDE = 16962 is NOT 4-aligned)
#define SFT_OFF  (((FEAT * WT_STRIDE + 3) / 4) * 4)   // 16964

__global__ __launch_bounds__(K2_T)
void feats_gemm_kernel(const float* __restrict__ W,
                       const float* __restrict__ bias,
                       float* __restrict__ out, int B)
{
    float* sWt = (float*)smem_raw;                    // 257*66 f
    float* sFt = sWt + SFT_OFF;                       // 16B-aligned

    const int t = threadIdx.x;
    const int row0 = blockIdx.x * K2_TM;

    // stage W transposed: sWt[k][o] = W[o][k]  (coalesced gmem reads)
    for (int i = t; i < OUT_DIM * FEAT; i += K2_T) {
        int o = i / FEAT;
        int k = i - o * FEAT;
        sWt[k * WT_STRIDE + o] = W[i];
    }
    // stage feats transposed: sFt[k][r] = feats[row0+r][k]
    const float* fin = g_feats + (size_t)row0 * FEAT;
    const int nrows = min(K2_TM, B - row0);
    for (int i = t; i < nrows * FEAT; i += K2_T) {
        int r = i / FEAT;
        int k = i - r * FEAT;
        sFt[k * FT_STRIDE + r] = fin[i];
    }
    __syncthreads();

    const int rg = t >> 5;     // row group 0..7  (rows rg*4 .. rg*4+3), const per warp
    const int cp = t & 31;     // col pair  0..31 (cols cp*2, cp*2+1)

    float acc00 = 0.f, acc01 = 0.f;
    float acc10 = 0.f, acc11 = 0.f;
    float acc20 = 0.f, acc21 = 0.f;
    float acc30 = 0.f, acc31 = 0.f;

    const float* fa = sFt + rg * 4;
    const float* wb = sWt + cp * 2;
    #pragma unroll 4
    for (int k = 0; k < FEAT; k++) {
        float4 a = *(const float4*)(fa + k * FT_STRIDE);   // broadcast (same addr per warp)
        float2 b = *(const float2*)(wb + k * WT_STRIDE);   // conflict-free LDS.64
        acc00 = fmaf(a.x, b.x, acc00);  acc01 = fmaf(a.x, b.y, acc01);
        acc10 = fmaf(a.y, b.x, acc10);  acc11 = fmaf(a.y, b.y, acc11);
        acc20 = fmaf(a.z, b.x, acc20);  acc21 = fmaf(a.z, b.y, acc21);
        acc30 = fmaf(a.w, b.x, acc30);  acc31 = fmaf(a.w, b.y, acc31);
    }

    float2 bb = *(const float2*)(bias + cp * 2);
    const int r0 = row0 + rg * 4;
    float2 o0 = make_float2(acc00 + bb.x, acc01 + bb.y);
    float2 o1 = make_float2(acc10 + bb.x, acc11 + bb.y);
    float2 o2 = make_float2(acc20 + bb.x, acc21 + bb.y);
    float2 o3 = make_float2(acc30 + bb.x, acc31 + bb.y);
    if (r0 + 3 < B) {
        *(float2*)(out + (size_t)(r0 + 0) * OUT_DIM + cp * 2) = o0;
        *(float2*)(out + (size_t)(r0 + 1) * OUT_DIM + cp * 2) = o1;
        *(float2*)(out + (size_t)(r0 + 2) * OUT_DIM + cp * 2) = o2;
        *(float2*)(out + (size_t)(r0 + 3) * OUT_DIM + cp * 2) = o3;
    } else {
        float2 os[4] = {o0, o1, o2, o3};
        for (int i = 0; i < 4; i++)
            if (r0 + i < B)
                *(float2*)(out + (size_t)(r0 + i) * OUT_DIM + cp * 2) = os[i];
    }
}

extern "C" void kernel_launch(void* const* d_in, const int* in_sizes, int n_in,
                              void* d_out, int out_size)
{
    const float* x = (const float*)d_in[0];
    const float* W = (const float*)d_in[1];
    const float* b = (const float*)d_in[2];
    float* out = (float*)d_out;

    const int B = in_sizes[0] / F_DIM;

    const size_t sm1 = (size_t)NWARPS * BINS * 4 + 2 * NWARPS * 4;            // 8320 B
    const size_t sm2 = ((size_t)SFT_OFF + (size_t)FEAT * FT_STRIDE) * 4;      // ~104868 B

    cudaFuncSetAttribute(hist_feats_kernel,
                         cudaFuncAttributeMaxDynamicSharedMemorySize, (int)sm1);
    cudaFuncSetAttribute(feats_gemm_kernel,
                         cudaFuncAttributeMaxDynamicSharedMemorySize, (int)sm2);

    hist_feats_kernel<<<B, NTHREADS, sm1>>>(x);
    feats_gemm_kernel<<<(B + K2_TM - 1) / K2_TM, K2_T, sm2>>>(W, b, out, B);
}

// round 8
// speedup vs baseline: 1.3917x; 1.0694x over previous
#include <cuda_runtime.h>

// Problem constants (fixed by setup_inputs)
#define F_DIM    16384
#define BINS     128
#define FEAT     (2*BINS + 1)     // 257
#define OUT_DIM  64
#define MAXB     4096

// ---- kernel 1: per-row histogram features ----
#define NTHREADS 512
#define NWARPS   (NTHREADS/32)    // 16
#define VPT      (F_DIM/NTHREADS) // 32 values per thread (8 float4)

// feats scratch: [B, 257] fp32 (static device global; no allocation)
__device__ float g_feats[(size_t)MAXB * FEAT];

extern __shared__ unsigned char smem_raw[];

__global__ __launch_bounds__(NTHREADS)
void hist_feats_kernel(const float* __restrict__ x)
{
    // smem: per-warp histograms + warp min/max partials (no data staging:
    // each thread re-bins its own register-resident values)
    int*   s_hist = (int*)smem_raw;                       // 16*128 ints = 8192 B
    float* s_wmin = (float*)(smem_raw + (size_t)NWARPS * BINS * 4);
    float* s_wmax = s_wmin + NWARPS;

    const int t    = threadIdx.x;
    const int wid  = t >> 5;
    const int lane = t & 31;
    const int row  = blockIdx.x;

    // zero per-warp histograms
    #pragma unroll
    for (int i = t; i < NWARPS * BINS; i += NTHREADS) s_hist[i] = 0;

    // Pass A: stream row HBM -> registers (float4), track min/max in flight
    const float4* xr = (const float4*)(x + (size_t)row * F_DIM);
    float4 v[VPT / 4];
    float lmin =  3.402823e38f;
    float lmax = -3.402823e38f;
    #pragma unroll
    for (int k = 0; k < VPT / 4; k++) {
        v[k] = xr[t + k * NTHREADS];
        lmin = fminf(lmin, fminf(fminf(v[k].x, v[k].y), fminf(v[k].z, v[k].w)));
        lmax = fmaxf(lmax, fmaxf(fmaxf(v[k].x, v[k].y), fmaxf(v[k].z, v[k].w)));
    }
    // warp reduce min/max
    #pragma unroll
    for (int s = 16; s; s >>= 1) {
        lmin = fminf(lmin, __shfl_xor_sync(0xffffffffu, lmin, s));
        lmax = fmaxf(lmax, __shfl_xor_sync(0xffffffffu, lmax, s));
    }
    if (lane == 0) { s_wmin[wid] = lmin; s_wmax[wid] = lmax; }
    __syncthreads();

    // block min/max
    float mn = s_wmin[0], mx = s_wmax[0];
    #pragma unroll
    for (int i = 1; i < NWARPS; i++) {
        mn = fminf(mn, s_wmin[i]);
        mx = fmaxf(mx, s_wmax[i]);
    }
    const float width = mx - mn;
    const float scale = (width > 0.0f) ? ((float)BINS / width) : 0.0f;

    // Pass B: histogram straight from registers, per-warp privatized counters
    int* hw = s_hist + wid * BINS;
    #pragma unroll
    for (int k = 0; k < VPT / 4; k++) {
        // (v - mn) >= 0 always, so int-truncation == floor; clamp top bin
        int b0 = min(BINS - 1, (int)((v[k].x - mn) * scale));
        int b1 = min(BINS - 1, (int)((v[k].y - mn) * scale));
        int b2 = min(BINS - 1, (int)((v[k].z - mn) * scale));
        int b3 = min(BINS - 1, (int)((v[k].w - mn) * scale));
        atomicAdd(&hw[b0], 1);
        atomicAdd(&hw[b1], 1);
        atomicAdd(&hw[b2], 1);
        atomicAdd(&hw[b3], 1);
    }
    __syncthreads();

    // reduce per-warp histograms + emit feats row
    float* outf = g_feats + (size_t)row * FEAT;
    if (t < BINS) {
        int c = 0;
        #pragma unroll
        for (int w = 0; w < NWARPS; w++) c += s_hist[w * BINS + t];
        outf[t] = (float)c * (1.0f / (float)F_DIM);   // density: sum == F exactly
    } else if (t < BINS + BINS + 1) {
        int i = t - BINS;
        outf[BINS + i] = mn + ((float)i * (1.0f / (float)BINS)) * width;
    }
}

// ---- kernel 2: out[B,64] = feats[B,257] @ W^T + b ----
// Natural-layout smem tiles (NO transpose, NO integer division in staging):
//   sW[o][k]  o<64, stride 257  (staged by pure linear float4 copy)
//   sF[r][k]  r<32, stride 257  (feats tile is contiguous in g_feats)
// Mainloop: A-frags are scalar LDS broadcasts (same addr warp-wide);
// B-frags are scalar LDS at rows c and c+32 -> bank (c+k)%32, conflict-free.
#define K2_TM   32
#define K2_T    256
#define W_ELEMS (OUT_DIM * FEAT)        // 16448  (4112 float4)
#define F_ELEMS (K2_TM * FEAT)          // 8224   (2056 float4)

__global__ __launch_bounds__(K2_T)
void feats_gemm_kernel(const float* __restrict__ W,
                       const float* __restrict__ bias,
                       float* __restrict__ out, int B)
{
    float* sW = (float*)smem_raw;             // 65792 B
    float* sF = sW + W_ELEMS;                 // offset 65792 B -> 16B aligned (16448%4==0)

    const int t = threadIdx.x;
    const int row0 = blockIdx.x * K2_TM;

    // stage W: linear float4 copy, 16 full rounds + 16-thread tail
    const float4* W4 = (const float4*)W;
    float4* sW4 = (float4*)sW;
    #pragma unroll
    for (int j = 0; j < 16; j++) sW4[t + j * K2_T] = W4[t + j * K2_T];  // 4096
    if (t < (W_ELEMS / 4 - 4096)) sW4[4096 + t] = W4[4096 + t];         // +16

    // stage feats: contiguous rows row0..row0+31; row0*FEAT % 4 == 0 -> aligned
    const float4* F4 = (const float4*)(g_feats + (size_t)row0 * FEAT);
    float4* sF4 = (float4*)sF;
    #pragma unroll
    for (int j = 0; j < 8; j++) sF4[t + j * K2_T] = F4[t + j * K2_T];   // 2048
    if (t < (F_ELEMS / 4 - 2048)) sF4[2048 + t] = F4[2048 + t];         // +8
    __syncthreads();

    const int rg = t >> 5;     // 0..7: rows rg*4 .. rg*4+3 (const per warp -> broadcast)
    const int c  = t & 31;     // output cols c and c+32

    const float* fa = sF + rg * 4 * FEAT;
    const float* w0 = sW + c * FEAT;
    const float* w1 = sW + (c + 32) * FEAT;

    float acc00 = 0.f, acc01 = 0.f;
    float acc10 = 0.f, acc11 = 0.f;
    float acc20 = 0.f, acc21 = 0.f;
    float acc30 = 0.f, acc31 = 0.f;

    #pragma unroll 4
    for (int k = 0; k < FEAT; k++) {
        float b0 = w0[k];                 // conflict-free (stride 257, bank (c+k)%32)
        float b1 = w1[k];                 // conflict-free
        float a0 = fa[k];                 // broadcast
        float a1 = fa[FEAT + k];          // broadcast
        float a2 = fa[2 * FEAT + k];      // broadcast
        float a3 = fa[3 * FEAT + k];      // broadcast
        acc00 = fmaf(a0, b0, acc00);  acc01 = fmaf(a0, b1, acc01);
        acc10 = fmaf(a1, b0, acc10);  acc11 = fmaf(a1, b1, acc11);
        acc20 = fmaf(a2, b0, acc20);  acc21 = fmaf(a2, b1, acc21);
        acc30 = fmaf(a3, b0, acc30);  acc31 = fmaf(a3, b1, acc31);
    }

    const float bb0 = bias[c];
    const float bb1 = bias[c + 32];
    const int r0 = row0 + rg * 4;
    float accs[4][2] = {{acc00, acc01}, {acc10, acc11}, {acc20, acc21}, {acc30, acc31}};
    #pragma unroll
    for (int i = 0; i < 4; i++) {
        if (r0 + i < B) {
            out[(size_t)(r0 + i) * OUT_DIM + c]      = accs[i][0] + bb0;
            out[(size_t)(r0 + i) * OUT_DIM + c + 32] = accs[i][1] + bb1;
        }
    }
}

extern "C" void kernel_launch(void* const* d_in, const int* in_sizes, int n_in,
                              void* d_out, int out_size)
{
    const float* x = (const float*)d_in[0];
    const float* W = (const float*)d_in[1];
    const float* b = (const float*)d_in[2];
    float* out = (float*)d_out;

    const int B = in_sizes[0] / F_DIM;

    const size_t sm1 = (size_t)NWARPS * BINS * 4 + 2 * NWARPS * 4;        // 8320 B
    const size_t sm2 = (size_t)(W_ELEMS + F_ELEMS) * 4;                   // 98688 B

    cudaFuncSetAttribute(hist_feats_kernel,
                         cudaFuncAttributeMaxDynamicSharedMemorySize, (int)sm1);
    cudaFuncSetAttribute(feats_gemm_kernel,
                         cudaFuncAttributeMaxDynamicSharedMemorySize, (int)sm2);

    hist_feats_kernel<<<B, NTHREADS, sm1>>>(x);
    feats_gemm_kernel<<<(B + K2_TM - 1) / K2_TM, K2_T, sm2>>>(W, b, out, B);
}